// round 7
// baseline (speedup 1.0000x reference)
#include <cuda_runtime.h>

// SORF fused: out[m] = (1/64) * sum_a alpha . cos( (1/16) H (D_s ⊙ (rep[m,a] @ red[s])) + bias_s ),
// s = charges[m,a]. Atoms grouped by charge, dense chunk table (4 atoms/CTA).
//   phase 1: GEMV (f32x2 FMA, 4-col quads, depth-4 prefetch, r-split x4, atom-split x2)
//   phase 2: warp = (atom, j-quarter); FWHT(256) in registers+shfl; signs via LOP3 from Dmat.

#define ATOMS 4
#define NATOMS 2048           // M*A
#define MAXCHUNK 515

__device__ int g_count[4];
__device__ int g_list[4 * NATOMS];
__device__ int g_tabS[MAXCHUNK];
__device__ int g_tabStart[MAXCHUNK];
__device__ int g_nchunks;

// ---- prep: smem-staged charges, warp-ballot compaction, chunk table ----
__global__ void prep_kernel(const int* __restrict__ charges, float* __restrict__ out) {
    __shared__ int chS[NATOMS];
    __shared__ int cntS[4];
    const int tid = threadIdx.x;          // 256 threads
    if (tid < 32) out[tid] = 0.0f;
    #pragma unroll
    for (int i = 0; i < NATOMS / 256; ++i) chS[tid + 256 * i] = charges[tid + 256 * i];
    __syncthreads();
    const int lane = tid & 31;
    const int w = tid >> 5;               // warp w handles charge s = w
    if (w < 4) {
        int cnt = 0;
        const unsigned lt = (1u << lane) - 1u;
        #pragma unroll 1
        for (int base = 0; base < NATOMS; base += 32) {
            int c = chS[base + lane];
            unsigned m = __ballot_sync(0xffffffffu, c == w);
            if (c == w) g_list[w * NATOMS + cnt + __popc(m & lt)] = base + lane;
            cnt += __popc(m);
        }
        if (lane == 0) { g_count[w] = cnt; cntS[w] = cnt; }
    }
    __syncthreads();
    int offs[5];
    offs[0] = 0;
    #pragma unroll
    for (int s = 0; s < 4; ++s) offs[s + 1] = offs[s] + ((cntS[s] + ATOMS - 1) / ATOMS);
    for (int c = tid; c < offs[4]; c += 256) {
        int s = (c >= offs[1]) + (c >= offs[2]) + (c >= offs[3]);
        g_tabS[c] = s;
        g_tabStart[c] = (c - offs[s]) * ATOMS;
    }
    if (tid == 0) g_nchunks = offs[4];
}

typedef unsigned long long ull;
__device__ __forceinline__ void ffma2(ull& acc, ull a, ull b) {
    asm("fma.rn.f32x2 %0, %1, %2, %0;" : "+l"(acc) : "l"(a), "l"(b));
}
__device__ __forceinline__ ull pack2(float a, float b) {
    ull r; asm("mov.b64 %0, {%1, %2};" : "=l"(r) : "f"(a), "f"(b)); return r;
}
__device__ __forceinline__ float2 unpack2(ull v) {
    float2 r; asm("mov.b64 {%0, %1}, %2;" : "=f"(r.x), "=f"(r.y) : "l"(v)); return r;
}

#define BFLY(a, b) do { float t_ = (a); (a) = t_ + (b); (b) = t_ - (b); } while (0)
__device__ __forceinline__ float sgnx(float x, float d) {   // x * sign(d) : 1 LOP3
    return __uint_as_float(__float_as_uint(x) ^ (__float_as_uint(d) & 0x80000000u));
}

__global__ void __launch_bounds__(512, 3) sorf_kernel(
    const float* __restrict__ rep,
    const float* __restrict__ reductors,
    const float* __restrict__ Dmat,
    const float* __restrict__ bias,
    const float* __restrict__ alpha,
    float* __restrict__ out)
{
    const int c = blockIdx.x;
    if (c >= g_nchunks) return;
    const int s = g_tabS[c];
    const int start = g_tabStart[c];
    const int n = g_count[s];
    const int cnt = min(ATOMS, n - start);

    __shared__ ull repdupS[ATOMS * 512];      // {v,v} pairs, 16 KB
    __shared__ float projS[4 * ATOMS * 256];  // [rh][atom][256], 16 KB
    __shared__ int atomsS[ATOMS];
    __shared__ float wpartS[16];

    const int tid = threadIdx.x;
    const int lane = tid & 31;
    const int w = tid >> 5;                   // 16 warps

    if (tid < ATOMS) atomsS[tid] = (tid < cnt) ? g_list[s * NATOMS + start + tid] : -1;
    __syncthreads();

    // fill duplicated rep tile: repdup[atom][r] = {rep_r, rep_r}
    {
        int ai = tid >> 7, q = tid & 127;     // 4 atoms x 128 float4
        int atom = atomsS[ai];
        float4 v = (atom >= 0) ? ((const float4*)rep)[(size_t)atom * 128 + q]
                               : make_float4(0.f, 0.f, 0.f, 0.f);
        ull* d = repdupS + ai * 512 + q * 4;
        d[0] = pack2(v.x, v.x); d[1] = pack2(v.y, v.y);
        d[2] = pack2(v.z, v.z); d[3] = pack2(v.w, v.w);
    }
    __syncthreads();

    // ---------------- Phase 1: proj = rep @ red[s]  (raw, scaled later)
    // thread = (c4: 64 col-quads, rh: 4 row-quarters, ath: 2 atom-pairs); 128 rows each.
    {
        const int c4 = tid & 63;
        const int rh = (tid >> 6) & 3;
        const int ath = tid >> 8;
        const int a0 = ath * 2;

        const ulonglong2* rbase = (const ulonglong2*)(reductors + (size_t)s * 131072)
                                  + (size_t)(rh * 128) * 64 + c4;
        const ulonglong2* rpA = (const ulonglong2*)(repdupS + (a0 + 0) * 512 + rh * 128);
        const ulonglong2* rpB = (const ulonglong2*)(repdupS + (a0 + 1) * 512 + rh * 128);

        ull accA0 = 0, accA1 = 0, accB0 = 0, accB1 = 0;
        ulonglong2 buf0 = rbase[0], buf1 = rbase[64], buf2 = rbase[128], buf3 = rbase[192];

        #pragma unroll 1
        for (int r = 0; r < 128; r += 4) {
            ulonglong2 c0 = buf0, c1 = buf1, c2 = buf2, c3 = buf3;
            if (r + 4 < 128) {
                buf0 = rbase[(r + 4) * 64]; buf1 = rbase[(r + 5) * 64];
                buf2 = rbase[(r + 6) * 64]; buf3 = rbase[(r + 7) * 64];
            }
            ulonglong2 pa0 = rpA[r >> 1], pa1 = rpA[(r >> 1) + 1];
            ulonglong2 pb0 = rpB[r >> 1], pb1 = rpB[(r >> 1) + 1];
            ffma2(accA0, pa0.x, c0.x); ffma2(accA1, pa0.x, c0.y);
            ffma2(accB0, pb0.x, c0.x); ffma2(accB1, pb0.x, c0.y);
            ffma2(accA0, pa0.y, c1.x); ffma2(accA1, pa0.y, c1.y);
            ffma2(accB0, pb0.y, c1.x); ffma2(accB1, pb0.y, c1.y);
            ffma2(accA0, pa1.x, c2.x); ffma2(accA1, pa1.x, c2.y);
            ffma2(accB0, pb1.x, c2.x); ffma2(accB1, pb1.x, c2.y);
            ffma2(accA0, pa1.y, c3.x); ffma2(accA1, pa1.y, c3.y);
            ffma2(accB0, pb1.y, c3.x); ffma2(accB1, pb1.y, c3.y);
        }

        float2* pp = (float2*)projS;
        int ia = (rh * 4 + a0) * 128 + c4 * 2;
        int ib = (rh * 4 + a0 + 1) * 128 + c4 * 2;
        pp[ia] = unpack2(accA0); pp[ia + 1] = unpack2(accA1);
        pp[ib] = unpack2(accB0); pp[ib + 1] = unpack2(accB1);
    }
    __syncthreads();

    // ---------------- Phase 2: warp = (atom ai, j-quarter jq); 8 stacks each
    // x[c] holds p = 4*lane+c ; x[4+c] holds p = 128+4*lane+c
    const int ai = w >> 2;
    const int jq = w & 3;
    const int atom = atomsS[ai];
    float partial = 0.f;

    if (atom >= 0) {
        const float4* pjq = (const float4*)projS;      // [rh][atom][64 float4]
        float4 xa4, xb4;
        {
            float4 t0 = pjq[(0 * 4 + ai) * 64 + lane];
            float4 t1 = pjq[(1 * 4 + ai) * 64 + lane];
            float4 t2 = pjq[(2 * 4 + ai) * 64 + lane];
            float4 t3 = pjq[(3 * 4 + ai) * 64 + lane];
            xa4.x = (t0.x + t1.x + t2.x + t3.x) * 0.0625f;
            xa4.y = (t0.y + t1.y + t2.y + t3.y) * 0.0625f;
            xa4.z = (t0.z + t1.z + t2.z + t3.z) * 0.0625f;
            xa4.w = (t0.w + t1.w + t2.w + t3.w) * 0.0625f;
            t0 = pjq[(0 * 4 + ai) * 64 + 32 + lane];
            t1 = pjq[(1 * 4 + ai) * 64 + 32 + lane];
            t2 = pjq[(2 * 4 + ai) * 64 + 32 + lane];
            t3 = pjq[(3 * 4 + ai) * 64 + 32 + lane];
            xb4.x = (t0.x + t1.x + t2.x + t3.x) * 0.0625f;
            xb4.y = (t0.y + t1.y + t2.y + t3.y) * 0.0625f;
            xb4.z = (t0.z + t1.z + t2.z + t3.z) * 0.0625f;
            xb4.w = (t0.w + t1.w + t2.w + t3.w) * 0.0625f;
        }

        const float4* dbase = (const float4*)(Dmat + (size_t)s * 8192) + lane;
        const float4* bbase = (const float4*)(bias + (size_t)s * 8192) + lane;
        const float4* abase = (const float4*)alpha + lane;
        const float sg0 = (lane & 1) ? -1.f : 1.f;
        const float sg1 = (lane & 2) ? -1.f : 1.f;
        const float sg2 = (lane & 4) ? -1.f : 1.f;
        const float sg3 = (lane & 8) ? -1.f : 1.f;
        const float sg4 = (lane & 16) ? -1.f : 1.f;

        #pragma unroll 1
        for (int j = 8 * jq; j < 8 * jq + 8; ++j) {
            float4 d0 = __ldg(dbase + j * 64);
            float4 d1 = __ldg(dbase + j * 64 + 32);
            float x0 = sgnx(xa4.x, d0.x), x1 = sgnx(xa4.y, d0.y);
            float x2 = sgnx(xa4.z, d0.z), x3 = sgnx(xa4.w, d0.w);
            float x4 = sgnx(xb4.x, d1.x), x5 = sgnx(xb4.y, d1.y);
            float x6 = sgnx(xb4.z, d1.z), x7 = sgnx(xb4.w, d1.w);

            // register butterflies: h=1, h=2, h=128
            BFLY(x0, x1); BFLY(x2, x3); BFLY(x4, x5); BFLY(x6, x7);
            BFLY(x0, x2); BFLY(x1, x3); BFLY(x4, x6); BFLY(x5, x7);
            BFLY(x0, x4); BFLY(x1, x5); BFLY(x2, x6); BFLY(x3, x7);

            // cross-lane butterflies: h = 4,8,16,32,64
            #define SSTAGE(m, sg)                                                  \
                x0 = fmaf(x0, sg, __shfl_xor_sync(0xffffffffu, x0, m));            \
                x1 = fmaf(x1, sg, __shfl_xor_sync(0xffffffffu, x1, m));            \
                x2 = fmaf(x2, sg, __shfl_xor_sync(0xffffffffu, x2, m));            \
                x3 = fmaf(x3, sg, __shfl_xor_sync(0xffffffffu, x3, m));            \
                x4 = fmaf(x4, sg, __shfl_xor_sync(0xffffffffu, x4, m));            \
                x5 = fmaf(x5, sg, __shfl_xor_sync(0xffffffffu, x5, m));            \
                x6 = fmaf(x6, sg, __shfl_xor_sync(0xffffffffu, x6, m));            \
                x7 = fmaf(x7, sg, __shfl_xor_sync(0xffffffffu, x7, m));
            SSTAGE(1, sg0) SSTAGE(2, sg1) SSTAGE(4, sg2) SSTAGE(8, sg3) SSTAGE(16, sg4)
            #undef SSTAGE

            float4 b0 = __ldg(bbase + j * 64);
            float4 b1 = __ldg(bbase + j * 64 + 32);
            float4 a0 = __ldg(abase + j * 64);
            float4 a1 = __ldg(abase + j * 64 + 32);
            partial = fmaf(__cosf(x0 + b0.x), a0.x, partial);
            partial = fmaf(__cosf(x1 + b0.y), a0.y, partial);
            partial = fmaf(__cosf(x2 + b0.z), a0.z, partial);
            partial = fmaf(__cosf(x3 + b0.w), a0.w, partial);
            partial = fmaf(__cosf(x4 + b1.x), a1.x, partial);
            partial = fmaf(__cosf(x5 + b1.y), a1.y, partial);
            partial = fmaf(__cosf(x6 + b1.z), a1.z, partial);
            partial = fmaf(__cosf(x7 + b1.w), a1.w, partial);
        }

        #pragma unroll
        for (int o = 16; o; o >>= 1) partial += __shfl_xor_sync(0xffffffffu, partial, o);
    }

    if (lane == 0) wpartS[w] = partial;
    __syncthreads();
    if (tid < ATOMS) {
        int atom2 = atomsS[tid];
        if (atom2 >= 0) {
            float v = wpartS[tid * 4] + wpartS[tid * 4 + 1] + wpartS[tid * 4 + 2] + wpartS[tid * 4 + 3];
            atomicAdd(&out[atom2 >> 6], v * 0.015625f);   // FEAT_NORM = 1/64
        }
    }
}

extern "C" void kernel_launch(void* const* d_in, const int* in_sizes, int n_in,
                              void* d_out, int out_size) {
    (void)in_sizes; (void)n_in; (void)out_size;
    const float* rep       = (const float*)d_in[0];
    const int*   charges   = (const int*)d_in[1];
    const float* reductors = (const float*)d_in[2];
    const float* Dmat      = (const float*)d_in[3];
    const float* bias      = (const float*)d_in[4];
    const float* alpha     = (const float*)d_in[5];
    float* out = (float*)d_out;

    prep_kernel<<<1, 256>>>(charges, out);
    sorf_kernel<<<MAXCHUNK, 512>>>(rep, reductors, Dmat, bias, alpha, out);
}

// round 8
// speedup vs baseline: 3.3045x; 3.3045x over previous
#include <cuda_runtime.h>

// SORF fused: out[m] = (1/64) * sum_a alpha . cos( (1/16) H (D_s ⊙ (rep[m,a] @ red[s])) + bias_s ),
// s = charges[m,a]. Atoms grouped by charge, dense chunk table (8 atoms/CTA).
//   phase 1: GEMV, f32x2 FMA; thread = (col-quad, row-slice) x all 8 atoms;
//            reductors read ONCE per CTA; rh-partials merged via smem float atomics.
//   phase 2: warp = (atom, j-half); FWHT(256) registers+shfl; signs from ballot bitmask;
//            bias overlaid into the rep smem region. All phase-2 operands smem/L1-hot.

#define ATOMS 8
#define NATOMS 2048           // M*A
#define MAXCHUNK 260

__device__ int g_count[4];
__device__ int g_list[4 * NATOMS];
__device__ int g_tabS[MAXCHUNK];
__device__ int g_tabStart[MAXCHUNK];
__device__ int g_nchunks;

// ---- prep: smem-staged charges, warp-ballot compaction, dense chunk table ----
__global__ void prep_kernel(const int* __restrict__ charges, float* __restrict__ out) {
    __shared__ int chS[NATOMS];
    __shared__ int cntS[4];
    const int tid = threadIdx.x;          // 256 threads
    if (tid < 32) out[tid] = 0.0f;
    #pragma unroll
    for (int i = 0; i < NATOMS / 256; ++i) chS[tid + 256 * i] = charges[tid + 256 * i];
    __syncthreads();
    const int lane = tid & 31;
    const int w = tid >> 5;               // warp w handles charge s = w
    if (w < 4) {
        int cnt = 0;
        const unsigned lt = (1u << lane) - 1u;
        #pragma unroll 1
        for (int base = 0; base < NATOMS; base += 32) {
            int c = chS[base + lane];
            unsigned m = __ballot_sync(0xffffffffu, c == w);
            if (c == w) g_list[w * NATOMS + cnt + __popc(m & lt)] = base + lane;
            cnt += __popc(m);
        }
        if (lane == 0) { g_count[w] = cnt; cntS[w] = cnt; }
    }
    __syncthreads();
    int offs[5];
    offs[0] = 0;
    #pragma unroll
    for (int s = 0; s < 4; ++s) offs[s + 1] = offs[s] + ((cntS[s] + ATOMS - 1) / ATOMS);
    for (int c = tid; c < offs[4]; c += 256) {
        int s = (c >= offs[1]) + (c >= offs[2]) + (c >= offs[3]);
        g_tabS[c] = s;
        g_tabStart[c] = (c - offs[s]) * ATOMS;
    }
    if (tid == 0) g_nchunks = offs[4];
}

typedef unsigned long long ull;
__device__ __forceinline__ void ffma2(ull& acc, ull a, ull b) {
    asm("fma.rn.f32x2 %0, %1, %2, %0;" : "+l"(acc) : "l"(a), "l"(b));
}
__device__ __forceinline__ ull pack2(float a, float b) {
    ull r; asm("mov.b64 %0, {%1, %2};" : "=l"(r) : "f"(a), "f"(b)); return r;
}
__device__ __forceinline__ float2 unpack2(ull v) {
    float2 r; asm("mov.b64 {%0, %1}, %2;" : "=f"(r.x), "=f"(r.y) : "l"(v)); return r;
}

#define BFLY(a, b) do { float t_ = (a); (a) = t_ + (b); (b) = t_ - (b); } while (0)

__global__ void __launch_bounds__(512, 2) sorf_kernel(
    const float* __restrict__ rep,
    const float* __restrict__ reductors,
    const float* __restrict__ Dmat,
    const float* __restrict__ bias,
    const float* __restrict__ alpha,
    float* __restrict__ out)
{
    const int c = blockIdx.x;
    if (c >= g_nchunks) return;
    const int s = g_tabS[c];
    const int start = g_tabStart[c];
    const int n = g_count[s];
    const int cnt = min(ATOMS, n - start);

    __shared__ ull repdupS[ATOMS * 512];      // {v,v} pairs 32 KB; phase 2: bias overlay
    __shared__ float projS[ATOMS * 256];      // 8 KB, accumulated via smem atomics
    __shared__ unsigned dbitsS[256];          // sign bits: 32 stacks x 8 words
    __shared__ int atomsS[ATOMS];
    __shared__ float wpartS[16];

    const int tid = threadIdx.x;
    const int lane = tid & 31;
    const int w = tid >> 5;                   // 16 warps

    if (tid < ATOMS) atomsS[tid] = (tid < cnt) ? g_list[s * NATOMS + start + tid] : -1;
    ((float4*)projS)[tid] = make_float4(0.f, 0.f, 0.f, 0.f);   // 512 float4 = 2048 floats
    __syncthreads();

    // fill duplicated rep tile: repdup[atom][r] = {rep_r, rep_r}
    {
        #pragma unroll
        for (int it = 0; it < 2; ++it) {
            int idx = tid + 512 * it;            // 1024 float4 slots = 8 atoms * 128
            int ai = idx >> 7, q = idx & 127;
            int atom = atomsS[ai];
            float4 v = (atom >= 0) ? ((const float4*)rep)[(size_t)atom * 128 + q]
                                   : make_float4(0.f, 0.f, 0.f, 0.f);
            ull* d = repdupS + ai * 512 + q * 4;
            d[0] = pack2(v.x, v.x); d[1] = pack2(v.y, v.y);
            d[2] = pack2(v.z, v.z); d[3] = pack2(v.w, v.w);
        }
    }
    __syncthreads();

    // ---------------- Phase 1: proj = rep @ red[s]; reductors read once per CTA.
    // thread = (c4: 64 col-quads, rh: 8 row-slices of 64 rows), all 8 atoms.
    {
        const int c4 = tid & 63;
        const int rh = tid >> 6;
        const int r0 = rh * 64;
        const ulonglong2* rbase = (const ulonglong2*)(reductors + (size_t)s * 131072)
                                  + (size_t)r0 * 64 + c4;

        ull acc0[8], acc1[8];
        #pragma unroll
        for (int a = 0; a < 8; ++a) { acc0[a] = 0ull; acc1[a] = 0ull; }

        ulonglong2 bufA = rbase[0];
        ulonglong2 bufB = rbase[64];

        #pragma unroll 1
        for (int rr = 0; rr < 64; rr += 2) {
            ulonglong2 ca = bufA, cb = bufB;
            if (rr + 2 < 64) { bufA = rbase[(rr + 2) * 64]; bufB = rbase[(rr + 3) * 64]; }
            const ulonglong2* rp = (const ulonglong2*)(repdupS + r0 + rr);
            #pragma unroll
            for (int a = 0; a < 8; ++a) {
                ulonglong2 p = rp[a * 256];    // broadcast LDS.128: {row rr dup, row rr+1 dup}
                ffma2(acc0[a], p.x, ca.x); ffma2(acc1[a], p.x, ca.y);
                ffma2(acc0[a], p.y, cb.x); ffma2(acc1[a], p.y, cb.y);
            }
        }

        #pragma unroll
        for (int a = 0; a < 8; ++a) {
            float2 v0 = unpack2(acc0[a]);
            float2 v1 = unpack2(acc1[a]);
            float* pp = projS + a * 256 + c4 * 4;
            atomicAdd(pp + 0, v0.x * 0.0625f);
            atomicAdd(pp + 1, v0.y * 0.0625f);
            atomicAdd(pp + 2, v1.x * 0.0625f);
            atomicAdd(pp + 3, v1.y * 0.0625f);
        }
    }
    __syncthreads();

    // bias -> smem overlay (repdup no longer needed), D sign bits via ballot
    {
        float4* dst = (float4*)repdupS;
        const float4* src = (const float4*)(bias + (size_t)s * 8192);
        #pragma unroll
        for (int it = 0; it < 4; ++it) dst[tid + 512 * it] = src[tid + 512 * it];
        const float* dsrc = Dmat + (size_t)s * 8192;
        #pragma unroll 1
        for (int k = 0; k < 16; ++k) {           // 16 warps x 16 words = 256
            int word = w * 16 + k;
            float dv = dsrc[word * 32 + lane];
            unsigned b = __ballot_sync(0xffffffffu, dv < 0.0f);
            if (lane == 0) dbitsS[word] = b;
        }
    }
    __syncthreads();

    // ---------------- Phase 2: warp = (atom ai, j-half jh); 16 stacks each
    // x[c] holds p = 4*lane+c ; x[4+c] holds p = 128+4*lane+c
    const int ai = w >> 1;
    const int jh = w & 1;
    const int atom = atomsS[ai];
    float partial = 0.f;

    if (atom >= 0) {
        const float4* pj4 = (const float4*)(projS + ai * 256);
        const float4* bb4 = (const float4*)repdupS;
        const float4* al4 = (const float4*)alpha;
        const int wsh = 4 * (lane & 7);
        const int widx = lane >> 3;
        const float sg0 = (lane & 1) ? -1.f : 1.f;
        const float sg1 = (lane & 2) ? -1.f : 1.f;
        const float sg2 = (lane & 4) ? -1.f : 1.f;
        const float sg3 = (lane & 8) ? -1.f : 1.f;
        const float sg4 = (lane & 16) ? -1.f : 1.f;

        const float4 xa4 = pj4[lane];        // invariant over j
        const float4 xb4 = pj4[lane + 32];

        #pragma unroll 1
        for (int j = 16 * jh; j < 16 * jh + 16; ++j) {
            unsigned n0 = dbitsS[j * 8 + widx] >> wsh;
            unsigned n1 = dbitsS[j * 8 + 4 + widx] >> wsh;
            float x0 = __uint_as_float(__float_as_uint(xa4.x) ^ ((n0 << 31) & 0x80000000u));
            float x1 = __uint_as_float(__float_as_uint(xa4.y) ^ ((n0 << 30) & 0x80000000u));
            float x2 = __uint_as_float(__float_as_uint(xa4.z) ^ ((n0 << 29) & 0x80000000u));
            float x3 = __uint_as_float(__float_as_uint(xa4.w) ^ ((n0 << 28) & 0x80000000u));
            float x4 = __uint_as_float(__float_as_uint(xb4.x) ^ ((n1 << 31) & 0x80000000u));
            float x5 = __uint_as_float(__float_as_uint(xb4.y) ^ ((n1 << 30) & 0x80000000u));
            float x6 = __uint_as_float(__float_as_uint(xb4.z) ^ ((n1 << 29) & 0x80000000u));
            float x7 = __uint_as_float(__float_as_uint(xb4.w) ^ ((n1 << 28) & 0x80000000u));

            // register butterflies: h=1, h=2, h=128
            BFLY(x0, x1); BFLY(x2, x3); BFLY(x4, x5); BFLY(x6, x7);
            BFLY(x0, x2); BFLY(x1, x3); BFLY(x4, x6); BFLY(x5, x7);
            BFLY(x0, x4); BFLY(x1, x5); BFLY(x2, x6); BFLY(x3, x7);

            // cross-lane butterflies: h = 4,8,16,32,64
            #define SSTAGE(m, sg)                                                  \
                x0 = fmaf(x0, sg, __shfl_xor_sync(0xffffffffu, x0, m));            \
                x1 = fmaf(x1, sg, __shfl_xor_sync(0xffffffffu, x1, m));            \
                x2 = fmaf(x2, sg, __shfl_xor_sync(0xffffffffu, x2, m));            \
                x3 = fmaf(x3, sg, __shfl_xor_sync(0xffffffffu, x3, m));            \
                x4 = fmaf(x4, sg, __shfl_xor_sync(0xffffffffu, x4, m));            \
                x5 = fmaf(x5, sg, __shfl_xor_sync(0xffffffffu, x5, m));            \
                x6 = fmaf(x6, sg, __shfl_xor_sync(0xffffffffu, x6, m));            \
                x7 = fmaf(x7, sg, __shfl_xor_sync(0xffffffffu, x7, m));
            SSTAGE(1, sg0) SSTAGE(2, sg1) SSTAGE(4, sg2) SSTAGE(8, sg3) SSTAGE(16, sg4)
            #undef SSTAGE

            float4 b0 = bb4[j * 64 + lane];
            float4 b1 = bb4[j * 64 + 32 + lane];
            float4 a0 = __ldg(&al4[j * 64 + lane]);
            float4 a1 = __ldg(&al4[j * 64 + 32 + lane]);
            partial = fmaf(__cosf(x0 + b0.x), a0.x, partial);
            partial = fmaf(__cosf(x1 + b0.y), a0.y, partial);
            partial = fmaf(__cosf(x2 + b0.z), a0.z, partial);
            partial = fmaf(__cosf(x3 + b0.w), a0.w, partial);
            partial = fmaf(__cosf(x4 + b1.x), a1.x, partial);
            partial = fmaf(__cosf(x5 + b1.y), a1.y, partial);
            partial = fmaf(__cosf(x6 + b1.z), a1.z, partial);
            partial = fmaf(__cosf(x7 + b1.w), a1.w, partial);
        }

        #pragma unroll
        for (int o = 16; o; o >>= 1) partial += __shfl_xor_sync(0xffffffffu, partial, o);
    }

    if (lane == 0) wpartS[w] = partial;
    __syncthreads();
    if (jh == 0 && lane == 0 && atom >= 0)
        atomicAdd(&out[atom >> 6], (wpartS[w] + wpartS[w + 1]) * 0.015625f);  // FEAT_NORM = 1/64

}

extern "C" void kernel_launch(void* const* d_in, const int* in_sizes, int n_in,
                              void* d_out, int out_size) {
    (void)in_sizes; (void)n_in; (void)out_size;
    const float* rep       = (const float*)d_in[0];
    const int*   charges   = (const int*)d_in[1];
    const float* reductors = (const float*)d_in[2];
    const float* Dmat      = (const float*)d_in[3];
    const float* bias      = (const float*)d_in[4];
    const float* alpha     = (const float*)d_in[5];
    float* out = (float*)d_out;

    prep_kernel<<<1, 256>>>(charges, out);
    sorf_kernel<<<MAXCHUNK, 512>>>(rep, reductors, Dmat, bias, alpha, out);
}